// round 9
// baseline (speedup 1.0000x reference)
#include <cuda_runtime.h>
#include <math.h>

#define T 4096
#define E 300
#define HID 512
#define G4 2048          // 4*HID
#define TAGS 12
#define NEGV -10000.0f
#define NB 32            // persistent blocks per direction in LSTM kernel

// ---------------- static device scratch (no allocations allowed) ----------------
__device__ float d_xg[2][T * G4];                  // 2 x 32 MB: precomputed input projections
__device__ unsigned long long d_Hx[2][T * HID];    // packed (tag<<32 | h_bits); tag = t+1
__device__ float d_feats[T * TAGS];
__device__ unsigned long long d_bp[T];             // packed backpointers: 12 nibbles per step

// fma.rn.f32x2 (FFMA2): numerics cleared vs scalar FFMA in R3/R4 control.
#define FMA2(d, a, b, c) \
    asm("fma.rn.f32x2 %0, %1, %2, %3;" : "=l"(d) : "l"(a), "l"(b), "l"(c))

// ---------------- zero d_Hx (graph replays must redo identical work) ----------------
__global__ void init_kernel() {
    unsigned int i = blockIdx.x * 1024 + threadIdx.x;    // 2M float4s = 32MB
    ((float4*)d_Hx)[i] = make_float4(0.f, 0.f, 0.f, 0.f);
}

// ---------------- xg = emb[sentence] @ Wih^T + (bih + bhh) ----------------
// grid (T/32, 2048/256), block 256. Each block: 32 timesteps x 256 rows.
__global__ void __launch_bounds__(256) xg_kernel(
    int dir,
    const int*   __restrict__ sent,
    const float* __restrict__ embt,
    const float* __restrict__ Wih,
    const float* __restrict__ bih,
    const float* __restrict__ bhh)
{
    __shared__ __align__(16) float es[E * 32];   // es[k*32 + t]
    int t0 = blockIdx.x * 32;
    for (int i = threadIdx.x; i < 32 * E; i += 256) {
        int tt = i / E, k = i - tt * E;
        es[k * 32 + tt] = embt[(long long)sent[t0 + tt] * E + k];
    }
    __syncthreads();

    int r = blockIdx.y * 256 + threadIdx.x;
    const float* w = Wih + (long long)r * E;
    float bias = bih[r] + bhh[r];
    float acc[32];
#pragma unroll
    for (int t = 0; t < 32; t++) acc[t] = bias;

    for (int k = 0; k < E; k++) {
        float wv = __ldg(w + k);
        const float4* e4 = (const float4*)(es + k * 32);
#pragma unroll
        for (int q = 0; q < 8; q++) {
            float4 e = e4[q];
            acc[4 * q + 0] += wv * e.x;
            acc[4 * q + 1] += wv * e.y;
            acc[4 * q + 2] += wv * e.z;
            acc[4 * q + 3] += wv * e.w;
        }
    }
    float* xg = d_xg[dir];
#pragma unroll
    for (int t = 0; t < 32; t++)
        xg[(long long)(t0 + t) * G4 + r] = acc[t];
}

// ---------------- persistent BiLSTM recurrence (sync-minimal) ----------------
// 64 blocks (32 fwd, 32 bwd), 256 threads; all co-resident.
// Block b owns units [16b,16b+16). Warp w owns 2 COMPLETE units (2w,2w+1):
// 8 full gate rows x 512 cols. Lane l: row rr=l>>2 (gate gI=rr>>1, sub-unit
// su=rr&1), col quarter q=l&3 -> 128 weights/lane (FFMA2-packed).
// Per step, per warp (no cross-warp reduce, no part[] smem):
//   dot from h_buf[s&1] -> 2x shfl_down quarter-reduce -> 4x shfl gate gather
//   lanes 0,1: + xg, activation chain, ONE st.release.gpu.u64 of
//              (t+1)<<32|h_bits  (exact R8-proven protocol)
//   all lanes: poll own 64-word share with 2 parallel ld.acquire.gpu.u64
//              spins; stage into h_buf[(s+1)&1]
//   ONE __syncthreads per step (double buffer removes the read/write hazard)
__global__ void __launch_bounds__(256, 1) lstm_kernel(
    const float* __restrict__ Whh_f,
    const float* __restrict__ Whh_b)
{
    const int bx  = blockIdx.x;
    const int dir = bx >> 5;
    const int b   = bx & 31;
    const float* Whh = dir ? Whh_b : Whh_f;
    const float* xg  = d_xg[dir];
    unsigned long long* Hx = d_Hx[dir];

    const int tid = threadIdx.x;
    const int w = tid >> 5, l = tid & 31;
    const int rr = l >> 2;                  // 0..7 row within warp
    const int q  = l & 3;                   // col quarter (128 cols)
    const int gI = rr >> 1;                 // gate 0..3 (i,f,g,o)
    const int su = rr & 1;                  // sub-unit 0/1
    const int unit = b * 16 + 2 * w + su;   // global hidden unit of this row
    const int grow = gI * HID + unit;       // global gate row (2048-space)

    // 128 weights per lane, packed as 64 u64 pairs for FFMA2
    unsigned long long wreg[64];
    {
        const ulonglong2* wp =
            (const ulonglong2*)(Whh + (long long)grow * HID + q * 128);
#pragma unroll
        for (int i = 0; i < 32; i++) {
            ulonglong2 v = wp[i];
            wreg[2 * i]     = v.x;
            wreg[2 * i + 1] = v.y;
        }
    }

    __shared__ __align__(16) float h_buf[2][HID];

    float c = 0.f;                 // cell state: valid in lanes 0,1 (unit 2w+l)
    float xgv[4] = {0.f, 0.f, 0.f, 0.f};

    ((float2*)h_buf[0])[tid] = make_float2(0.f, 0.f);
    if (l < 2) {
        int t0 = dir ? (T - 1) : 0;
        int myu = b * 16 + 2 * w + l;
#pragma unroll
        for (int g = 0; g < 4; g++)
            xgv[g] = xg[(long long)t0 * G4 + g * HID + myu];
    }
    __syncthreads();

    const int su2 = l & 1;                  // gather helper (lanes 0,1 use result)

    for (int s = 0; s < T; s++) {
        const int t = dir ? (T - 1 - s) : s;
        const unsigned want = (unsigned)t + 1u;

        // ---- full-row partial dot over this lane's 128-col quarter ----
        float sum;
        {
            unsigned long long a0 = 0ull, a1 = 0ull;
            const ulonglong2* h2 =
                (const ulonglong2*)(h_buf[s & 1] + (q << 7));
#pragma unroll
            for (int i = 0; i < 32; i++) {
                ulonglong2 hv = h2[i];
                FMA2(a0, wreg[2 * i],     hv.x, a0);
                FMA2(a1, wreg[2 * i + 1], hv.y, a1);
            }
            float x0, x1, x2, x3;
            asm("mov.b64 {%0,%1}, %2;" : "=f"(x0), "=f"(x1) : "l"(a0));
            asm("mov.b64 {%0,%1}, %2;" : "=f"(x2), "=f"(x3) : "l"(a1));
            sum = (x0 + x1) + (x2 + x3);
        }
        // quarter reduce: lanes rr*4..rr*4+3 -> total in lane rr*4
        sum += __shfl_down_sync(0xffffffffu, sum, 2);
        sum += __shfl_down_sync(0xffffffffu, sum, 1);

        // gather the 4 gate sums for unit su2 (valid rows at lanes 8*g+4*su2)
        float gi = __shfl_sync(0xffffffffu, sum, 4 * su2);
        float gf = __shfl_sync(0xffffffffu, sum, 8 + 4 * su2);
        float gg = __shfl_sync(0xffffffffu, sum, 16 + 4 * su2);
        float go = __shfl_sync(0xffffffffu, sum, 24 + 4 * su2);

        if (l < 2) {
            float g0 = gi + xgv[0];
            float g1 = gf + xgv[1];
            float g2 = gg + xgv[2];
            float g3 = go + xgv[3];

            float ig = __fdividef(1.f, 1.f + __expf(-g0));
            float fg = __fdividef(1.f, 1.f + __expf(-g1));
            float og = __fdividef(1.f, 1.f + __expf(-g3));
            float tg = __fdividef(2.f, 1.f + __expf(-2.f * g2)) - 1.f;
            c = fg * c + ig * tg;
            float th = __fdividef(2.f, 1.f + __expf(-2.f * c)) - 1.f;
            float hh = og * th;

            int myu = b * 16 + 2 * w + l;
            unsigned long long pv =
                ((unsigned long long)want << 32) |
                (unsigned long long)__float_as_uint(hh);
            asm volatile("st.release.gpu.global.u64 [%0], %1;"
                         :: "l"(Hx + (long long)t * HID + myu), "l"(pv)
                         : "memory");

            // prefetch next step's xg (a full step of latency slack)
            if (s + 1 < T) {
                int tn = dir ? (t - 1) : (t + 1);
#pragma unroll
                for (int g = 0; g < 4; g++)
                    xgv[g] = __ldcg(xg + (long long)tn * G4 + g * HID + myu);
            }
        }

        if (s == T - 1) break;

        // ---- poll own 64-word share: 2 parallel acquire spins per lane ----
        {
            const unsigned long long* base = Hx + (long long)t * HID;
            const unsigned long long* p0 = base + (w << 6) + l;
            const unsigned long long* p1 = p0 + 32;
            unsigned long long v0 = 0, v1 = 0;
            bool d0 = false, d1 = false;
            do {
                if (!d0) {
                    asm volatile("ld.acquire.gpu.global.u64 %0, [%1];"
                                 : "=l"(v0) : "l"(p0) : "memory");
                    d0 = (unsigned)(v0 >> 32) == want;
                }
                if (!d1) {
                    asm volatile("ld.acquire.gpu.global.u64 %0, [%1];"
                                 : "=l"(v1) : "l"(p1) : "memory");
                    d1 = (unsigned)(v1 >> 32) == want;
                }
            } while (!(d0 && d1));
            float* dst = h_buf[(s + 1) & 1];
            dst[(w << 6) + l]      = __uint_as_float((unsigned)v0);
            dst[(w << 6) + 32 + l] = __uint_as_float((unsigned)v1);
        }
        __syncthreads();   // ONE barrier per step
    }
}

// ---------------- feats = [h_f, h_b] @ W_out^T + b_out ----------------
// Reads h out of the packed array: float4 = (h0,tag0,h1,tag1) in fp32 lanes.
__global__ void __launch_bounds__(128) feats_kernel(
    const float* __restrict__ W_out,
    const float* __restrict__ b_out)
{
    __shared__ __align__(16) float hb[2 * HID];
    int tid = threadIdx.x;
    int r = tid >> 3, cs = tid & 7;

    for (int tt = 0; tt < 32; tt++) {
        int t = blockIdx.x * 32 + tt;
        __syncthreads();
#pragma unroll
        for (int dir = 0; dir < 2; dir++) {
            const float4* src = (const float4*)(d_Hx[dir] + (long long)t * HID);
#pragma unroll
            for (int k = 0; k < 2; k++) {
                int i = k * 128 + tid;           // 0..255 float4s (= 512 packed words)
                float4 v = src[i];
                hb[dir * HID + 2 * i]     = v.x;  // h lives in the low word
                hb[dir * HID + 2 * i + 1] = v.z;
            }
        }
        __syncthreads();
        if (tid < 96) {
            const float4* wv = (const float4*)(W_out + r * 1024 + cs * 128);
            const float4* hv = (const float4*)(hb + cs * 128);
            float s0 = 0.f, s1 = 0.f, s2 = 0.f, s3 = 0.f;
#pragma unroll
            for (int i = 0; i < 32; i++) {
                float4 a = __ldg(wv + i);
                float4 bq = hv[i];
                s0 += a.x * bq.x; s1 += a.y * bq.y;
                s2 += a.z * bq.z; s3 += a.w * bq.w;
            }
            float sum = (s0 + s1) + (s2 + s3);
#pragma unroll
            for (int o = 4; o >= 1; o >>= 1)
                sum += __shfl_down_sync(0xffffffffu, sum, o);
            if (cs == 0)
                d_feats[t * TAGS + r] = sum + b_out[r];
        }
    }
}

// ---------------- Viterbi: forward scan + packed backtrace ----------------
__global__ void viterbi_kernel(const float* __restrict__ trans,
                               float* __restrict__ out)
{
    __shared__ unsigned long long bps[T];
    int l = threadIdx.x;

    float tr[TAGS];
    if (l < TAGS) {
#pragma unroll
        for (int p = 0; p < TAGS; p++) tr[p] = trans[l * TAGS + p];
    } else {
#pragma unroll
        for (int p = 0; p < TAGS; p++) tr[p] = 0.f;
    }

    float fv = (l == 10) ? 0.f : NEGV;   // START = 10
    float featnext = (l < TAGS) ? d_feats[l] : 0.f;

    for (int t = 0; t < T; t++) {
        float feat = featnext;
        if (t + 1 < T && l < TAGS) featnext = d_feats[(t + 1) * TAGS + l];

        float m = -3.4e38f; int am = 0;
#pragma unroll
        for (int p = 0; p < TAGS; p++) {
            float v = __shfl_sync(0xffffffffu, fv, p) + tr[p];
            if (v > m) { m = v; am = p; }
        }
        unsigned lo = (l < 8)              ? ((unsigned)am << (4 * l))       : 0u;
        unsigned hi = (l >= 8 && l < TAGS) ? ((unsigned)am << (4 * (l - 8))) : 0u;
        lo = __reduce_add_sync(0xffffffffu, lo);
        hi = __reduce_add_sync(0xffffffffu, hi);
        if (l == 0) d_bp[t] = ((unsigned long long)hi << 32) | lo;

        fv = m + feat;
    }

    float term;
    if (l < TAGS) term = fv + trans[11 * TAGS + l];
    else          term = -3.4e38f;
    if (l == 11 || l == 10) term = NEGV;

    int best = 0; float sc = -3.4e38f;
#pragma unroll
    for (int p = 0; p < TAGS; p++) {
        float v = __shfl_sync(0xffffffffu, term, p);
        if (v > sc) { sc = v; best = p; }
    }

    for (int i = l; i < T; i += 32) bps[i] = d_bp[i];
    __syncwarp();

    if (l == 0) {
        out[0] = sc;
        out[T] = (float)best;            // path[T-1]
        int tag = best;
        for (int t = T - 1; t >= 1; t--) {
            int prev = (int)((bps[t] >> (4 * tag)) & 15ull);
            out[t] = (float)prev;        // path[t-1] = chain[t]
            tag = prev;
        }
    }
}

// ---------------- launch ----------------
extern "C" void kernel_launch(void* const* d_in, const int* in_sizes, int n_in,
                              void* d_out, int out_size)
{
    const int*   sent  = (const int*)d_in[0];
    const float* embt  = (const float*)d_in[1];
    const float* Wih_f = (const float*)d_in[2];
    const float* Whh_f = (const float*)d_in[3];
    const float* bih_f = (const float*)d_in[4];
    const float* bhh_f = (const float*)d_in[5];
    const float* Wih_b = (const float*)d_in[6];
    const float* Whh_b = (const float*)d_in[7];
    const float* bih_b = (const float*)d_in[8];
    const float* bhh_b = (const float*)d_in[9];
    const float* W_out = (const float*)d_in[10];
    const float* b_out = (const float*)d_in[11];
    const float* trans = (const float*)d_in[12];
    float* out = (float*)d_out;

    init_kernel<<<2048, 1024>>>();
    dim3 g(T / 32, G4 / 256);
    xg_kernel<<<g, 256>>>(0, sent, embt, Wih_f, bih_f, bhh_f);
    xg_kernel<<<g, 256>>>(1, sent, embt, Wih_b, bih_b, bhh_b);
    lstm_kernel<<<2 * NB, 256>>>(Whh_f, Whh_b);
    feats_kernel<<<128, 128>>>(W_out, b_out);
    viterbi_kernel<<<1, 32>>>(trans, out);
}

// round 10
// speedup vs baseline: 1.2540x; 1.2540x over previous
#include <cuda_runtime.h>
#include <math.h>

#define T 4096
#define E 300
#define HID 512
#define G4 2048          // 4*HID
#define TAGS 12
#define NEGV -10000.0f
#define NB 32            // persistent blocks per direction in LSTM kernel

// ---------------- static device scratch (no allocations allowed) ----------------
__device__ float d_xg[2][T * G4];                  // 2 x 32 MB: precomputed input projections
__device__ unsigned long long d_Hx[2][T * HID];    // packed (tag<<32 | h_bits); tag = t+1
__device__ float d_feats[T * TAGS];
__device__ unsigned long long d_bp[T];             // packed backpointers: 12 nibbles per step

// fma.rn.f32x2 (FFMA2): numerics cleared vs scalar FFMA in R3/R4 control.
#define FMA2(d, a, b, c) \
    asm("fma.rn.f32x2 %0, %1, %2, %3;" : "=l"(d) : "l"(a), "l"(b), "l"(c))

// MUFU.TANH: single-op tanh (sm_75+), abs err ~2^-11
__device__ __forceinline__ float tanh_fast(float x) {
    float r;
    asm("tanh.approx.f32 %0, %1;" : "=f"(r) : "f"(x));
    return r;
}
// sigmoid(x) = 0.5 + 0.5*tanh(x/2)
__device__ __forceinline__ float sigmoid_fast(float x) {
    return fmaf(tanh_fast(0.5f * x), 0.5f, 0.5f);
}

// ---------------- zero d_Hx (graph replays must redo identical work) ----------------
__global__ void init_kernel() {
    unsigned int i = blockIdx.x * 1024 + threadIdx.x;    // 2M float4s = 32MB
    ((float4*)d_Hx)[i] = make_float4(0.f, 0.f, 0.f, 0.f);
}

// ---------------- xg = emb[sentence] @ Wih^T + (bih + bhh) ----------------
// grid (T/32, 2048/256), block 256. Each block: 32 timesteps x 256 rows.
__global__ void __launch_bounds__(256) xg_kernel(
    int dir,
    const int*   __restrict__ sent,
    const float* __restrict__ embt,
    const float* __restrict__ Wih,
    const float* __restrict__ bih,
    const float* __restrict__ bhh)
{
    __shared__ __align__(16) float es[E * 32];   // es[k*32 + t]
    int t0 = blockIdx.x * 32;
    for (int i = threadIdx.x; i < 32 * E; i += 256) {
        int tt = i / E, k = i - tt * E;
        es[k * 32 + tt] = embt[(long long)sent[t0 + tt] * E + k];
    }
    __syncthreads();

    int r = blockIdx.y * 256 + threadIdx.x;
    const float* w = Wih + (long long)r * E;
    float bias = bih[r] + bhh[r];
    float acc[32];
#pragma unroll
    for (int t = 0; t < 32; t++) acc[t] = bias;

    for (int k = 0; k < E; k++) {
        float wv = __ldg(w + k);
        const float4* e4 = (const float4*)(es + k * 32);
#pragma unroll
        for (int q = 0; q < 8; q++) {
            float4 e = e4[q];
            acc[4 * q + 0] += wv * e.x;
            acc[4 * q + 1] += wv * e.y;
            acc[4 * q + 2] += wv * e.z;
            acc[4 * q + 3] += wv * e.w;
        }
    }
    float* xg = d_xg[dir];
#pragma unroll
    for (int t = 0; t < 32; t++)
        xg[(long long)(t0 + t) * G4 + r] = acc[t];
}

// ---------------- persistent BiLSTM recurrence ----------------
// 64 blocks (32 fwd, 32 bwd), 256 threads; all co-resident.
// Block b owns 16 hidden units -> 64 Whh gate rows.
// Warp w: col chunk cc=w>>1 (128 cols), local gate row lr=(w&1)*32+l.
// Per step:
//   all warps: FFMA2 partial dots -> part[4][64] -> syncA
//   warp 0 lanes<16: reduce + MUFU.TANH activations; ONE st.release.gpu.u64
//       of (t+1)<<32 | h_bits per lane  (R8-proven strong pair protocol)
//   warps 4,5 ONLY (64 lanes): poll 8 words each, all spins parallel.
//       (Fewer pollers -> producer stores queue behind fewer reads at LTS.)
//   syncB
__global__ void __launch_bounds__(256, 1) lstm_kernel(
    const float* __restrict__ Whh_f,
    const float* __restrict__ Whh_b)
{
    const int bx  = blockIdx.x;
    const int dir = bx >> 5;
    const int b   = bx & 31;
    const float* Whh = dir ? Whh_b : Whh_f;
    const float* xg  = d_xg[dir];
    unsigned long long* Hx = d_Hx[dir];

    const int tid = threadIdx.x;
    const int w = tid >> 5, l = tid & 31;
    const int cc = w >> 1;                  // 0..3 column chunk (128 cols)
    const int lr = (w & 1) * 32 + l;        // 0..63 local gate row
    const int grow = ((lr >> 4) << 9) + b * 16 + (lr & 15);  // global gate row

    // weights: 128 fp32 per thread, packed as 64 u64 pairs for FFMA2
    unsigned long long wreg[64];
    {
        const ulonglong2* wp =
            (const ulonglong2*)(Whh + (long long)grow * HID + cc * 128);
#pragma unroll
        for (int i = 0; i < 32; i++) {
            ulonglong2 v = wp[i];
            wreg[2 * i]     = v.x;
            wreg[2 * i + 1] = v.y;
        }
    }

    __shared__ __align__(16) float h_sh[HID];
    __shared__ float part[4][64];

    float c = 0.f;                 // cell state (warp 0 lanes 0-15)
    float xgv[4] = {0.f, 0.f, 0.f, 0.f};

    h_sh[tid] = 0.f;
    h_sh[tid + 256] = 0.f;
    if (w == 0 && l < 16) {
        int t0 = dir ? (T - 1) : 0;
#pragma unroll
        for (int g = 0; g < 4; g++)
            xgv[g] = xg[(long long)t0 * G4 + (g << 9) + b * 16 + l];
    }
    __syncthreads();

    for (int s = 0; s < T; s++) {
        const int t = dir ? (T - 1 - s) : s;
        const unsigned want = (unsigned)t + 1u;

        // ---- partial dot: lane gate-row x 128-col chunk (FFMA2) ----
        {
            unsigned long long a0 = 0ull, a1 = 0ull;
            const ulonglong2* h2 = (const ulonglong2*)(h_sh + (cc << 7));
#pragma unroll
            for (int i = 0; i < 32; i++) {
                ulonglong2 hv = h2[i];   // broadcast LDS.128 (uniform address)
                FMA2(a0, wreg[2 * i],     hv.x, a0);
                FMA2(a1, wreg[2 * i + 1], hv.y, a1);
            }
            float x0, x1, x2, x3;
            asm("mov.b64 {%0,%1}, %2;" : "=f"(x0), "=f"(x1) : "l"(a0));
            asm("mov.b64 {%0,%1}, %2;" : "=f"(x2), "=f"(x3) : "l"(a1));
            part[cc][lr] = (x0 + x1) + (x2 + x3);
        }
        __syncthreads();   // A: all partials in smem

        if (w == 0) {
            if (l < 16) {
                float g0 = part[0][l]      + part[1][l]      + part[2][l]      + part[3][l]      + xgv[0];
                float g1 = part[0][16 + l] + part[1][16 + l] + part[2][16 + l] + part[3][16 + l] + xgv[1];
                float g2 = part[0][32 + l] + part[1][32 + l] + part[2][32 + l] + part[3][32 + l] + xgv[2];
                float g3 = part[0][48 + l] + part[1][48 + l] + part[2][48 + l] + part[3][48 + l] + xgv[3];

                float ig = sigmoid_fast(g0);
                float fg = sigmoid_fast(g1);
                float og = sigmoid_fast(g3);
                float tg = tanh_fast(g2);
                c = fg * c + ig * tg;
                float hh = og * tanh_fast(c);

                // ONE strong ST.64: (t+1)<<32 | h_bits, release scope gpu
                unsigned long long pv =
                    ((unsigned long long)want << 32) |
                    (unsigned long long)__float_as_uint(hh);
                unsigned long long* hp = Hx + (long long)t * HID + b * 16 + l;
                asm volatile("st.release.gpu.global.u64 [%0], %1;"
                             :: "l"(hp), "l"(pv) : "memory");

                // prefetch next step's xg (a full step of latency slack)
                if (s + 1 < T) {
                    int tn = dir ? (t - 1) : (t + 1);
#pragma unroll
                    for (int g = 0; g < 4; g++)
                        xgv[g] = __ldcg(xg + (long long)tn * G4 + (g << 9) + b * 16 + l);
                }
            }
        } else if ((w == 4 || w == 5) && s + 1 < T) {
            // ---- 8 parallel acquire spins per lane (64 pollers total) ----
            const int cidx = ((w - 4) << 5) + l;           // 0..63
            const unsigned long long* base = Hx + (long long)t * HID;
            unsigned long long v[8];
            bool dn[8];
#pragma unroll
            for (int p = 0; p < 8; p++) { v[p] = 0; dn[p] = false; }
            bool all;
            do {
                all = true;
#pragma unroll
                for (int p = 0; p < 8; p++) {
                    if (!dn[p]) {
                        const unsigned long long* ap = base + (p << 6) + cidx;
                        asm volatile("ld.acquire.gpu.global.u64 %0, [%1];"
                                     : "=l"(v[p]) : "l"(ap) : "memory");
                        dn[p] = (unsigned)(v[p] >> 32) == want;
                        all &= dn[p];
                    }
                }
            } while (!all);
#pragma unroll
            for (int p = 0; p < 8; p++)
                h_sh[(p << 6) + cidx] = __uint_as_float((unsigned)v[p]);
        }
        __syncthreads();   // B: h(t) staged in smem for next step
    }
}

// ---------------- feats = [h_f, h_b] @ W_out^T + b_out ----------------
// Reads h out of the packed array: float4 = (h0,tag0,h1,tag1) in fp32 lanes.
__global__ void __launch_bounds__(128) feats_kernel(
    const float* __restrict__ W_out,
    const float* __restrict__ b_out)
{
    __shared__ __align__(16) float hb[2 * HID];
    int tid = threadIdx.x;
    int r = tid >> 3, cs = tid & 7;

    for (int tt = 0; tt < 32; tt++) {
        int t = blockIdx.x * 32 + tt;
        __syncthreads();
#pragma unroll
        for (int dir = 0; dir < 2; dir++) {
            const float4* src = (const float4*)(d_Hx[dir] + (long long)t * HID);
#pragma unroll
            for (int k = 0; k < 2; k++) {
                int i = k * 128 + tid;           // 0..255 float4s (= 512 packed words)
                float4 v = src[i];
                hb[dir * HID + 2 * i]     = v.x;  // h lives in the low word
                hb[dir * HID + 2 * i + 1] = v.z;
            }
        }
        __syncthreads();
        if (tid < 96) {
            const float4* wv = (const float4*)(W_out + r * 1024 + cs * 128);
            const float4* hv = (const float4*)(hb + cs * 128);
            float s0 = 0.f, s1 = 0.f, s2 = 0.f, s3 = 0.f;
#pragma unroll
            for (int i = 0; i < 32; i++) {
                float4 a = __ldg(wv + i);
                float4 bq = hv[i];
                s0 += a.x * bq.x; s1 += a.y * bq.y;
                s2 += a.z * bq.z; s3 += a.w * bq.w;
            }
            float sum = (s0 + s1) + (s2 + s3);
#pragma unroll
            for (int o = 4; o >= 1; o >>= 1)
                sum += __shfl_down_sync(0xffffffffu, sum, o);
            if (cs == 0)
                d_feats[t * TAGS + r] = sum + b_out[r];
        }
    }
}

// ---------------- Viterbi: forward scan + packed backtrace ----------------
__global__ void viterbi_kernel(const float* __restrict__ trans,
                               float* __restrict__ out)
{
    __shared__ unsigned long long bps[T];
    int l = threadIdx.x;

    float tr[TAGS];
    if (l < TAGS) {
#pragma unroll
        for (int p = 0; p < TAGS; p++) tr[p] = trans[l * TAGS + p];
    } else {
#pragma unroll
        for (int p = 0; p < TAGS; p++) tr[p] = 0.f;
    }

    float fv = (l == 10) ? 0.f : NEGV;   // START = 10
    float featnext = (l < TAGS) ? d_feats[l] : 0.f;

    for (int t = 0; t < T; t++) {
        float feat = featnext;
        if (t + 1 < T && l < TAGS) featnext = d_feats[(t + 1) * TAGS + l];

        float m = -3.4e38f; int am = 0;
#pragma unroll
        for (int p = 0; p < TAGS; p++) {
            float v = __shfl_sync(0xffffffffu, fv, p) + tr[p];
            if (v > m) { m = v; am = p; }
        }
        unsigned lo = (l < 8)              ? ((unsigned)am << (4 * l))       : 0u;
        unsigned hi = (l >= 8 && l < TAGS) ? ((unsigned)am << (4 * (l - 8))) : 0u;
        lo = __reduce_add_sync(0xffffffffu, lo);
        hi = __reduce_add_sync(0xffffffffu, hi);
        if (l == 0) d_bp[t] = ((unsigned long long)hi << 32) | lo;

        fv = m + feat;
    }

    float term;
    if (l < TAGS) term = fv + trans[11 * TAGS + l];
    else          term = -3.4e38f;
    if (l == 11 || l == 10) term = NEGV;

    int best = 0; float sc = -3.4e38f;
#pragma unroll
    for (int p = 0; p < TAGS; p++) {
        float v = __shfl_sync(0xffffffffu, term, p);
        if (v > sc) { sc = v; best = p; }
    }

    for (int i = l; i < T; i += 32) bps[i] = d_bp[i];
    __syncwarp();

    if (l == 0) {
        out[0] = sc;
        out[T] = (float)best;            // path[T-1]
        int tag = best;
        for (int t = T - 1; t >= 1; t--) {
            int prev = (int)((bps[t] >> (4 * tag)) & 15ull);
            out[t] = (float)prev;        // path[t-1] = chain[t]
            tag = prev;
        }
    }
}

// ---------------- launch ----------------
extern "C" void kernel_launch(void* const* d_in, const int* in_sizes, int n_in,
                              void* d_out, int out_size)
{
    const int*   sent  = (const int*)d_in[0];
    const float* embt  = (const float*)d_in[1];
    const float* Wih_f = (const float*)d_in[2];
    const float* Whh_f = (const float*)d_in[3];
    const float* bih_f = (const float*)d_in[4];
    const float* bhh_f = (const float*)d_in[5];
    const float* Wih_b = (const float*)d_in[6];
    const float* Whh_b = (const float*)d_in[7];
    const float* bih_b = (const float*)d_in[8];
    const float* bhh_b = (const float*)d_in[9];
    const float* W_out = (const float*)d_in[10];
    const float* b_out = (const float*)d_in[11];
    const float* trans = (const float*)d_in[12];
    float* out = (float*)d_out;

    init_kernel<<<2048, 1024>>>();
    dim3 g(T / 32, G4 / 256);
    xg_kernel<<<g, 256>>>(0, sent, embt, Wih_f, bih_f, bhh_f);
    xg_kernel<<<g, 256>>>(1, sent, embt, Wih_b, bih_b, bhh_b);
    lstm_kernel<<<2 * NB, 256>>>(Whh_f, Whh_b);
    feats_kernel<<<128, 128>>>(W_out, b_out);
    viterbi_kernel<<<1, 32>>>(trans, out);
}

// round 11
// speedup vs baseline: 1.8428x; 1.4696x over previous
#include <cuda_runtime.h>
#include <math.h>

#define T 4096
#define E 300
#define HID 512
#define G4 2048          // 4*HID
#define TAGS 12
#define NEGV -10000.0f
#define NB 32            // persistent blocks per direction in LSTM kernel

// ---------------- static device scratch (no allocations allowed) ----------------
__device__ float d_xg[2][T * G4];          // 2 x 32 MB: precomputed input projections
__device__ float d_Hs[2][T * HID];         // 2 x 8 MB : per-step hidden states
__device__ unsigned int d_cnt[2][T];       // per-(dir,step) arrival counters
__device__ float d_feats[T * TAGS];
__device__ unsigned long long d_bp[T];     // packed backpointers: 12 nibbles per step

// fma.rn.f32x2 (FFMA2): numerics cleared vs scalar FFMA (R3/R4 bit-identical)
#define FMA2(d, a, b, c) \
    asm("fma.rn.f32x2 %0, %1, %2, %3;" : "=l"(d) : "l"(a), "l"(b), "l"(c))

// MUFU.TANH path cleared in R10 (passed, rel_err 5.7e-6)
__device__ __forceinline__ float tanh_fast(float x) {
    float r;
    asm("tanh.approx.f32 %0, %1;" : "=f"(r) : "f"(x));
    return r;
}
__device__ __forceinline__ float sigmoid_fast(float x) {
    return fmaf(tanh_fast(0.5f * x), 0.5f, 0.5f);
}

// ---------------- zero step counters (graph replays reuse state) ----------------
__global__ void init_kernel() {
    int i = blockIdx.x * 1024 + threadIdx.x;
    if (i < 2 * T) ((unsigned int*)d_cnt)[i] = 0u;
}

// ---------------- xg = emb[sentence] @ Wih^T + (bih + bhh), both dirs ----------------
// grid (T/32, 2048/256, 2), block 256. Each block: 32 timesteps x 256 rows.
__global__ void __launch_bounds__(256) xg_kernel(
    const int*   __restrict__ sent,
    const float* __restrict__ embt,
    const float* __restrict__ Wih_f,
    const float* __restrict__ bih_f,
    const float* __restrict__ bhh_f,
    const float* __restrict__ Wih_b,
    const float* __restrict__ bih_b,
    const float* __restrict__ bhh_b)
{
    const int dir = blockIdx.z;
    const float* Wih = dir ? Wih_b : Wih_f;
    const float* bih = dir ? bih_b : bih_f;
    const float* bhh = dir ? bhh_b : bhh_f;

    __shared__ __align__(16) float es[E * 32];   // es[k*32 + t]
    int t0 = blockIdx.x * 32;
    for (int i = threadIdx.x; i < 32 * E; i += 256) {
        int tt = i / E, k = i - tt * E;
        es[k * 32 + tt] = embt[(long long)sent[t0 + tt] * E + k];
    }
    __syncthreads();

    int r = blockIdx.y * 256 + threadIdx.x;
    const float* w = Wih + (long long)r * E;
    float bias = bih[r] + bhh[r];
    float acc[32];
#pragma unroll
    for (int t = 0; t < 32; t++) acc[t] = bias;

    for (int k = 0; k < E; k++) {
        float wv = __ldg(w + k);
        const float4* e4 = (const float4*)(es + k * 32);
#pragma unroll
        for (int q = 0; q < 8; q++) {
            float4 e = e4[q];
            acc[4 * q + 0] += wv * e.x;
            acc[4 * q + 1] += wv * e.y;
            acc[4 * q + 2] += wv * e.z;
            acc[4 * q + 3] += wv * e.w;
        }
    }
    float* xg = d_xg[dir];
#pragma unroll
    for (int t = 0; t < 32; t++)
        xg[(long long)(t0 + t) * G4 + r] = acc[t];
}

// ---------------- persistent BiLSTM recurrence ----------------
// 64 blocks (32 fwd, 32 bwd), 256 threads; all co-resident.
// Block b owns 16 hidden units -> 64 Whh gate rows.
// Warp w: col chunk cc=w>>1 (128 cols), local gate row lr=(w&1)*32+l.
// Per step:
//   all warps: FFMA2 partial dots -> part[4][64] -> syncA
//   warp 0: lanes<16 reduce + MUFU.TANH act + PARALLEL st.cg of own h float;
//           __syncwarp; lane 0 red.release.gpu.add.u32 on cnt[t]
//           (REDG: fire-and-forget, no return trip; release orders the
//            warp's data stores via the syncwarp happens-before chain)
//   warp 1: all 32 lanes poll cnt[t] (SAME word -> 1 coalesced request)
//           with ld.acquire.gpu until ==32, then bulk-reload h(t)
//           (4 coalesced float4/lane) into h_sh
//   syncB
__global__ void __launch_bounds__(256, 1) lstm_kernel(
    const float* __restrict__ Whh_f,
    const float* __restrict__ Whh_b)
{
    const int bx  = blockIdx.x;
    const int dir = bx >> 5;
    const int b   = bx & 31;
    const float* Whh = dir ? Whh_b : Whh_f;
    const float* xg  = d_xg[dir];
    float* Hst = d_Hs[dir];
    unsigned int* cnt = d_cnt[dir];

    const int tid = threadIdx.x;
    const int w = tid >> 5, l = tid & 31;
    const int cc = w >> 1;                  // 0..3 column chunk (128 cols)
    const int lr = (w & 1) * 32 + l;        // 0..63 local gate row
    const int grow = ((lr >> 4) << 9) + b * 16 + (lr & 15);  // global gate row

    // weights: 128 fp32 per thread, packed as 64 u64 pairs for FFMA2
    unsigned long long wreg[64];
    {
        const ulonglong2* wp =
            (const ulonglong2*)(Whh + (long long)grow * HID + cc * 128);
#pragma unroll
        for (int i = 0; i < 32; i++) {
            ulonglong2 v = wp[i];
            wreg[2 * i]     = v.x;
            wreg[2 * i + 1] = v.y;
        }
    }

    __shared__ __align__(16) float h_sh[HID];
    __shared__ float part[4][64];

    float c = 0.f;                 // cell state (warp 0 lanes 0-15)
    float xgv[4] = {0.f, 0.f, 0.f, 0.f};

    h_sh[tid] = 0.f;
    h_sh[tid + 256] = 0.f;
    if (w == 0 && l < 16) {
        int t0 = dir ? (T - 1) : 0;
#pragma unroll
        for (int g = 0; g < 4; g++)
            xgv[g] = xg[(long long)t0 * G4 + (g << 9) + b * 16 + l];
    }
    __syncthreads();

    for (int s = 0; s < T; s++) {
        const int t = dir ? (T - 1 - s) : s;

        // ---- partial dot: lane gate-row x 128-col chunk (FFMA2) ----
        {
            unsigned long long a0 = 0ull, a1 = 0ull;
            const ulonglong2* h2 = (const ulonglong2*)(h_sh + (cc << 7));
#pragma unroll
            for (int i = 0; i < 32; i++) {
                ulonglong2 hv = h2[i];   // broadcast LDS.128 (uniform address)
                FMA2(a0, wreg[2 * i],     hv.x, a0);
                FMA2(a1, wreg[2 * i + 1], hv.y, a1);
            }
            float x0, x1, x2, x3;
            asm("mov.b64 {%0,%1}, %2;" : "=f"(x0), "=f"(x1) : "l"(a0));
            asm("mov.b64 {%0,%1}, %2;" : "=f"(x2), "=f"(x3) : "l"(a1));
            part[cc][lr] = (x0 + x1) + (x2 + x3);
        }
        __syncthreads();   // A: all partials in smem

        if (w == 0) {
            if (l < 16) {
                float g0 = part[0][l]      + part[1][l]      + part[2][l]      + part[3][l]      + xgv[0];
                float g1 = part[0][16 + l] + part[1][16 + l] + part[2][16 + l] + part[3][16 + l] + xgv[1];
                float g2 = part[0][32 + l] + part[1][32 + l] + part[2][32 + l] + part[3][32 + l] + xgv[2];
                float g3 = part[0][48 + l] + part[1][48 + l] + part[2][48 + l] + part[3][48 + l] + xgv[3];

                float ig = sigmoid_fast(g0);
                float fg = sigmoid_fast(g1);
                float og = sigmoid_fast(g3);
                float tg = tanh_fast(g2);
                c = fg * c + ig * tg;
                float hh = og * tanh_fast(c);

                // parallel 64B coalesced data store (weak, .cg)
                asm volatile("st.global.cg.f32 [%0], %1;"
                             :: "l"(Hst + (long long)t * HID + b * 16 + l),
                                "f"(hh) : "memory");

                // prefetch next step's xg (a full step of latency slack)
                if (s + 1 < T) {
                    int tn = dir ? (t - 1) : (t + 1);
#pragma unroll
                    for (int g = 0; g < 4; g++)
                        xgv[g] = __ldcg(xg + (long long)tn * G4 + (g << 9) + b * 16 + l);
                }
            }
            __syncwarp();   // all lanes' h stores ordered before the release
            if (l == 0) {
                asm volatile("red.release.gpu.global.add.u32 [%0], %1;"
                             :: "l"(cnt + t), "r"(1u) : "memory");
            }
        } else if (w == 1 && s + 1 < T) {
            // ---- poll ONE counter word (1 coalesced request per sweep) ----
            unsigned v;
            do {
                asm volatile("ld.acquire.gpu.global.u32 %0, [%1];"
                             : "=r"(v) : "l"(cnt + t) : "memory");
            } while (v < (unsigned)NB);

            // ---- bulk reload h(t): 4 coalesced float4 loads per lane ----
            const float4* hp4 = (const float4*)(Hst + (long long)t * HID);
            float4 r0 = __ldcg(hp4 + l);
            float4 r1 = __ldcg(hp4 + 32 + l);
            float4 r2 = __ldcg(hp4 + 64 + l);
            float4 r3 = __ldcg(hp4 + 96 + l);
            float4* hs4 = (float4*)h_sh;
            hs4[l]      = r0;
            hs4[32 + l] = r1;
            hs4[64 + l] = r2;
            hs4[96 + l] = r3;
        }
        __syncthreads();   // B: h(t) staged in smem for next step
    }
}

// ---------------- feats = [h_f, h_b] @ W_out^T + b_out ----------------
__global__ void __launch_bounds__(128) feats_kernel(
    const float* __restrict__ W_out,
    const float* __restrict__ b_out)
{
    __shared__ __align__(16) float hb[2 * HID];
    int tid = threadIdx.x;
    int r = tid >> 3, cs = tid & 7;

    for (int tt = 0; tt < 32; tt++) {
        int t = blockIdx.x * 32 + tt;
        __syncthreads();
        ((float4*)hb)[tid]       = ((const float4*)(d_Hs[0] + (long long)t * HID))[tid];
        ((float4*)hb)[128 + tid] = ((const float4*)(d_Hs[1] + (long long)t * HID))[tid];
        __syncthreads();
        if (tid < 96) {
            const float4* wv = (const float4*)(W_out + r * 1024 + cs * 128);
            const float4* hv = (const float4*)(hb + cs * 128);
            float s0 = 0.f, s1 = 0.f, s2 = 0.f, s3 = 0.f;
#pragma unroll
            for (int i = 0; i < 32; i++) {
                float4 a = __ldg(wv + i);
                float4 bq = hv[i];
                s0 += a.x * bq.x; s1 += a.y * bq.y;
                s2 += a.z * bq.z; s3 += a.w * bq.w;
            }
            float sum = (s0 + s1) + (s2 + s3);
#pragma unroll
            for (int o = 4; o >= 1; o >>= 1)
                sum += __shfl_down_sync(0xffffffffu, sum, o);
            if (cs == 0)
                d_feats[t * TAGS + r] = sum + b_out[r];
        }
    }
}

// ---------------- Viterbi: forward scan + packed backtrace ----------------
__global__ void viterbi_kernel(const float* __restrict__ trans,
                               float* __restrict__ out)
{
    __shared__ unsigned long long bps[T];
    int l = threadIdx.x;

    float tr[TAGS];
    if (l < TAGS) {
#pragma unroll
        for (int p = 0; p < TAGS; p++) tr[p] = trans[l * TAGS + p];
    } else {
#pragma unroll
        for (int p = 0; p < TAGS; p++) tr[p] = 0.f;
    }

    float fv = (l == 10) ? 0.f : NEGV;   // START = 10
    float featnext = (l < TAGS) ? d_feats[l] : 0.f;

    for (int t = 0; t < T; t++) {
        float feat = featnext;
        if (t + 1 < T && l < TAGS) featnext = d_feats[(t + 1) * TAGS + l];

        float m = -3.4e38f; int am = 0;
#pragma unroll
        for (int p = 0; p < TAGS; p++) {
            float v = __shfl_sync(0xffffffffu, fv, p) + tr[p];
            if (v > m) { m = v; am = p; }
        }
        unsigned lo = (l < 8)              ? ((unsigned)am << (4 * l))       : 0u;
        unsigned hi = (l >= 8 && l < TAGS) ? ((unsigned)am << (4 * (l - 8))) : 0u;
        lo = __reduce_add_sync(0xffffffffu, lo);
        hi = __reduce_add_sync(0xffffffffu, hi);
        if (l == 0) d_bp[t] = ((unsigned long long)hi << 32) | lo;

        fv = m + feat;
    }

    float term;
    if (l < TAGS) term = fv + trans[11 * TAGS + l];
    else          term = -3.4e38f;
    if (l == 11 || l == 10) term = NEGV;

    int best = 0; float sc = -3.4e38f;
#pragma unroll
    for (int p = 0; p < TAGS; p++) {
        float v = __shfl_sync(0xffffffffu, term, p);
        if (v > sc) { sc = v; best = p; }
    }

    for (int i = l; i < T; i += 32) bps[i] = d_bp[i];
    __syncwarp();

    if (l == 0) {
        out[0] = sc;
        out[T] = (float)best;            // path[T-1]
        int tag = best;
        for (int t = T - 1; t >= 1; t--) {
            int prev = (int)((bps[t] >> (4 * tag)) & 15ull);
            out[t] = (float)prev;        // path[t-1] = chain[t]
            tag = prev;
        }
    }
}

// ---------------- launch ----------------
extern "C" void kernel_launch(void* const* d_in, const int* in_sizes, int n_in,
                              void* d_out, int out_size)
{
    const int*   sent  = (const int*)d_in[0];
    const float* embt  = (const float*)d_in[1];
    const float* Wih_f = (const float*)d_in[2];
    const float* Whh_f = (const float*)d_in[3];
    const float* bih_f = (const float*)d_in[4];
    const float* bhh_f = (const float*)d_in[5];
    const float* Wih_b = (const float*)d_in[6];
    const float* Whh_b = (const float*)d_in[7];
    const float* bih_b = (const float*)d_in[8];
    const float* bhh_b = (const float*)d_in[9];
    const float* W_out = (const float*)d_in[10];
    const float* b_out = (const float*)d_in[11];
    const float* trans = (const float*)d_in[12];
    float* out = (float*)d_out;

    init_kernel<<<8, 1024>>>();
    dim3 g(T / 32, G4 / 256, 2);
    xg_kernel<<<g, 256>>>(sent, embt, Wih_f, bih_f, bhh_f, Wih_b, bih_b, bhh_b);
    lstm_kernel<<<2 * NB, 256>>>(Whh_f, Whh_b);
    feats_kernel<<<128, 128>>>(W_out, b_out);
    viterbi_kernel<<<1, 32>>>(trans, out);
}

// round 12
// speedup vs baseline: 1.8644x; 1.0117x over previous
#include <cuda_runtime.h>
#include <math.h>

#define T 4096
#define E 300
#define HID 512
#define G4 2048          // 4*HID
#define TAGS 12
#define NEGV -10000.0f
#define NB 32            // persistent blocks per direction in LSTM kernel

// ---------------- static device scratch (no allocations allowed) ----------------
__device__ float d_xg[2][T * G4];          // 2 x 32 MB: precomputed input projections
__device__ float d_Hs[2][T * HID];         // 2 x 8 MB : per-step hidden states
__device__ unsigned int d_cnt[2][T];       // per-(dir,step) arrival counters
__device__ float d_feats[T * TAGS];
__device__ unsigned long long d_bp[T];     // packed backpointers: 12 nibbles per step

// fma.rn.f32x2 (FFMA2): numerics cleared vs scalar FFMA (R3/R4 bit-identical)
#define FMA2(d, a, b, c) \
    asm("fma.rn.f32x2 %0, %1, %2, %3;" : "=l"(d) : "l"(a), "l"(b), "l"(c))

// MUFU.TANH path cleared in R10/R11 (passed, rel_err 5.7e-6)
__device__ __forceinline__ float tanh_fast(float x) {
    float r;
    asm("tanh.approx.f32 %0, %1;" : "=f"(r) : "f"(x));
    return r;
}
__device__ __forceinline__ float sigmoid_fast(float x) {
    return fmaf(tanh_fast(0.5f * x), 0.5f, 0.5f);
}

// ---------------- zero step counters (graph replays reuse state) ----------------
__global__ void init_kernel() {
    int i = blockIdx.x * 1024 + threadIdx.x;
    if (i < 2 * T) ((unsigned int*)d_cnt)[i] = 0u;
}

// ---------------- xg = emb[sentence] @ Wih^T + (bih + bhh), both dirs ----------------
// grid (T/32, 2048/256, 2), block 256. Each block: 32 timesteps x 256 rows.
// Weights: float4 LDG (75 instead of 300 scalar). Inner loop: FFMA2 with
// packed accumulators (16 u64 = 32 timesteps), es read as ulonglong2.
__global__ void __launch_bounds__(256) xg_kernel(
    const int*   __restrict__ sent,
    const float* __restrict__ embt,
    const float* __restrict__ Wih_f,
    const float* __restrict__ bih_f,
    const float* __restrict__ bhh_f,
    const float* __restrict__ Wih_b,
    const float* __restrict__ bih_b,
    const float* __restrict__ bhh_b)
{
    const int dir = blockIdx.z;
    const float* Wih = dir ? Wih_b : Wih_f;
    const float* bih = dir ? bih_b : bih_f;
    const float* bhh = dir ? bhh_b : bhh_f;

    __shared__ __align__(16) float es[E * 32];   // es[k*32 + t]
    int t0 = blockIdx.x * 32;
    for (int i = threadIdx.x; i < 32 * E; i += 256) {
        int tt = i / E, k = i - tt * E;
        es[k * 32 + tt] = embt[(long long)sent[t0 + tt] * E + k];
    }
    __syncthreads();

    int r = blockIdx.y * 256 + threadIdx.x;
    const float4* w4 = (const float4*)(Wih + (long long)r * E);   // E=300 = 75 float4
    float bias = bih[r] + bhh[r];

    unsigned long long acc2[16];                  // 32 fp32 accumulators, packed
    {
        unsigned bb = __float_as_uint(bias);
        unsigned long long b2;
        asm("mov.b64 %0, {%1,%1};" : "=l"(b2) : "r"(bb));
#pragma unroll
        for (int i = 0; i < 16; i++) acc2[i] = b2;
    }

    for (int ko = 0; ko < 75; ko++) {
        float4 wq = __ldg(w4 + ko);
#pragma unroll
        for (int j = 0; j < 4; j++) {
            float wv = (j == 0) ? wq.x : (j == 1) ? wq.y : (j == 2) ? wq.z : wq.w;
            unsigned wb = __float_as_uint(wv);
            unsigned long long wvv;
            asm("mov.b64 %0, {%1,%1};" : "=l"(wvv) : "r"(wb));
            const ulonglong2* e2 = (const ulonglong2*)(es + (4 * ko + j) * 32);
#pragma unroll
            for (int q = 0; q < 8; q++) {
                ulonglong2 ev = e2[q];            // broadcast LDS.128
                FMA2(acc2[2 * q],     wvv, ev.x, acc2[2 * q]);
                FMA2(acc2[2 * q + 1], wvv, ev.y, acc2[2 * q + 1]);
            }
        }
    }

    float* xg = d_xg[dir];
#pragma unroll
    for (int i = 0; i < 16; i++) {
        float lo, hi;
        asm("mov.b64 {%0,%1}, %2;" : "=f"(lo), "=f"(hi) : "l"(acc2[i]));
        xg[(long long)(t0 + 2 * i)     * G4 + r] = lo;
        xg[(long long)(t0 + 2 * i + 1) * G4 + r] = hi;
    }
}

// ---------------- persistent BiLSTM recurrence (UNCHANGED from R11 best) ----------------
__global__ void __launch_bounds__(256, 1) lstm_kernel(
    const float* __restrict__ Whh_f,
    const float* __restrict__ Whh_b)
{
    const int bx  = blockIdx.x;
    const int dir = bx >> 5;
    const int b   = bx & 31;
    const float* Whh = dir ? Whh_b : Whh_f;
    const float* xg  = d_xg[dir];
    float* Hst = d_Hs[dir];
    unsigned int* cnt = d_cnt[dir];

    const int tid = threadIdx.x;
    const int w = tid >> 5, l = tid & 31;
    const int cc = w >> 1;                  // 0..3 column chunk (128 cols)
    const int lr = (w & 1) * 32 + l;        // 0..63 local gate row
    const int grow = ((lr >> 4) << 9) + b * 16 + (lr & 15);  // global gate row

    unsigned long long wreg[64];
    {
        const ulonglong2* wp =
            (const ulonglong2*)(Whh + (long long)grow * HID + cc * 128);
#pragma unroll
        for (int i = 0; i < 32; i++) {
            ulonglong2 v = wp[i];
            wreg[2 * i]     = v.x;
            wreg[2 * i + 1] = v.y;
        }
    }

    __shared__ __align__(16) float h_sh[HID];
    __shared__ float part[4][64];

    float c = 0.f;                 // cell state (warp 0 lanes 0-15)
    float xgv[4] = {0.f, 0.f, 0.f, 0.f};

    h_sh[tid] = 0.f;
    h_sh[tid + 256] = 0.f;
    if (w == 0 && l < 16) {
        int t0 = dir ? (T - 1) : 0;
#pragma unroll
        for (int g = 0; g < 4; g++)
            xgv[g] = xg[(long long)t0 * G4 + (g << 9) + b * 16 + l];
    }
    __syncthreads();

    for (int s = 0; s < T; s++) {
        const int t = dir ? (T - 1 - s) : s;

        // ---- partial dot: lane gate-row x 128-col chunk (FFMA2) ----
        {
            unsigned long long a0 = 0ull, a1 = 0ull;
            const ulonglong2* h2 = (const ulonglong2*)(h_sh + (cc << 7));
#pragma unroll
            for (int i = 0; i < 32; i++) {
                ulonglong2 hv = h2[i];   // broadcast LDS.128 (uniform address)
                FMA2(a0, wreg[2 * i],     hv.x, a0);
                FMA2(a1, wreg[2 * i + 1], hv.y, a1);
            }
            float x0, x1, x2, x3;
            asm("mov.b64 {%0,%1}, %2;" : "=f"(x0), "=f"(x1) : "l"(a0));
            asm("mov.b64 {%0,%1}, %2;" : "=f"(x2), "=f"(x3) : "l"(a1));
            part[cc][lr] = (x0 + x1) + (x2 + x3);
        }
        __syncthreads();   // A: all partials in smem

        if (w == 0) {
            if (l < 16) {
                float g0 = part[0][l]      + part[1][l]      + part[2][l]      + part[3][l]      + xgv[0];
                float g1 = part[0][16 + l] + part[1][16 + l] + part[2][16 + l] + part[3][16 + l] + xgv[1];
                float g2 = part[0][32 + l] + part[1][32 + l] + part[2][32 + l] + part[3][32 + l] + xgv[2];
                float g3 = part[0][48 + l] + part[1][48 + l] + part[2][48 + l] + part[3][48 + l] + xgv[3];

                float ig = sigmoid_fast(g0);
                float fg = sigmoid_fast(g1);
                float og = sigmoid_fast(g3);
                float tg = tanh_fast(g2);
                c = fg * c + ig * tg;
                float hh = og * tanh_fast(c);

                asm volatile("st.global.cg.f32 [%0], %1;"
                             :: "l"(Hst + (long long)t * HID + b * 16 + l),
                                "f"(hh) : "memory");

                if (s + 1 < T) {
                    int tn = dir ? (t - 1) : (t + 1);
#pragma unroll
                    for (int g = 0; g < 4; g++)
                        xgv[g] = __ldcg(xg + (long long)tn * G4 + (g << 9) + b * 16 + l);
                }
            }
            __syncwarp();   // all lanes' h stores ordered before the release
            if (l == 0) {
                asm volatile("red.release.gpu.global.add.u32 [%0], %1;"
                             :: "l"(cnt + t), "r"(1u) : "memory");
            }
        } else if (w == 1 && s + 1 < T) {
            unsigned v;
            do {
                asm volatile("ld.acquire.gpu.global.u32 %0, [%1];"
                             : "=r"(v) : "l"(cnt + t) : "memory");
            } while (v < (unsigned)NB);

            const float4* hp4 = (const float4*)(Hst + (long long)t * HID);
            float4 r0 = __ldcg(hp4 + l);
            float4 r1 = __ldcg(hp4 + 32 + l);
            float4 r2 = __ldcg(hp4 + 64 + l);
            float4 r3 = __ldcg(hp4 + 96 + l);
            float4* hs4 = (float4*)h_sh;
            hs4[l]      = r0;
            hs4[32 + l] = r1;
            hs4[64 + l] = r2;
            hs4[96 + l] = r3;
        }
        __syncthreads();   // B: h(t) staged in smem for next step
    }
}

// ---------------- feats = [h_f, h_b] @ W_out^T + b_out ----------------
// grid 256, block 128, 16 timesteps per block.
__global__ void __launch_bounds__(128) feats_kernel(
    const float* __restrict__ W_out,
    const float* __restrict__ b_out)
{
    __shared__ __align__(16) float hb[2 * HID];
    int tid = threadIdx.x;
    int r = tid >> 3, cs = tid & 7;

    for (int tt = 0; tt < 16; tt++) {
        int t = blockIdx.x * 16 + tt;
        __syncthreads();
        ((float4*)hb)[tid]       = ((const float4*)(d_Hs[0] + (long long)t * HID))[tid];
        ((float4*)hb)[128 + tid] = ((const float4*)(d_Hs[1] + (long long)t * HID))[tid];
        __syncthreads();
        if (tid < 96) {
            const float4* wv = (const float4*)(W_out + r * 1024 + cs * 128);
            const float4* hv = (const float4*)(hb + cs * 128);
            float s0 = 0.f, s1 = 0.f, s2 = 0.f, s3 = 0.f;
#pragma unroll
            for (int i = 0; i < 32; i++) {
                float4 a = __ldg(wv + i);
                float4 bq = hv[i];
                s0 += a.x * bq.x; s1 += a.y * bq.y;
                s2 += a.z * bq.z; s3 += a.w * bq.w;
            }
            float sum = (s0 + s1) + (s2 + s3);
#pragma unroll
            for (int o = 4; o >= 1; o >>= 1)
                sum += __shfl_down_sync(0xffffffffu, sum, o);
            if (cs == 0)
                d_feats[t * TAGS + r] = sum + b_out[r];
        }
    }
}

// ---------------- Viterbi: forward scan + packed backtrace ----------------
__global__ void viterbi_kernel(const float* __restrict__ trans,
                               float* __restrict__ out)
{
    __shared__ unsigned long long bps[T];
    int l = threadIdx.x;

    float tr[TAGS];
    if (l < TAGS) {
#pragma unroll
        for (int p = 0; p < TAGS; p++) tr[p] = trans[l * TAGS + p];
    } else {
#pragma unroll
        for (int p = 0; p < TAGS; p++) tr[p] = 0.f;
    }

    float fv = (l == 10) ? 0.f : NEGV;   // START = 10
    float featnext = (l < TAGS) ? d_feats[l] : 0.f;

    for (int t = 0; t < T; t++) {
        float feat = featnext;
        if (t + 1 < T && l < TAGS) featnext = d_feats[(t + 1) * TAGS + l];

        float m = -3.4e38f; int am = 0;
#pragma unroll
        for (int p = 0; p < TAGS; p++) {
            float v = __shfl_sync(0xffffffffu, fv, p) + tr[p];
            if (v > m) { m = v; am = p; }
        }
        unsigned lo = (l < 8)              ? ((unsigned)am << (4 * l))       : 0u;
        unsigned hi = (l >= 8 && l < TAGS) ? ((unsigned)am << (4 * (l - 8))) : 0u;
        lo = __reduce_add_sync(0xffffffffu, lo);
        hi = __reduce_add_sync(0xffffffffu, hi);
        if (l == 0) d_bp[t] = ((unsigned long long)hi << 32) | lo;

        fv = m + feat;
    }

    float term;
    if (l < TAGS) term = fv + trans[11 * TAGS + l];
    else          term = -3.4e38f;
    if (l == 11 || l == 10) term = NEGV;

    int best = 0; float sc = -3.4e38f;
#pragma unroll
    for (int p = 0; p < TAGS; p++) {
        float v = __shfl_sync(0xffffffffu, term, p);
        if (v > sc) { sc = v; best = p; }
    }

    for (int i = l; i < T; i += 32) bps[i] = d_bp[i];
    __syncwarp();

    if (l == 0) {
        out[0] = sc;
        out[T] = (float)best;            // path[T-1]
        int tag = best;
        for (int t = T - 1; t >= 1; t--) {
            int prev = (int)((bps[t] >> (4 * tag)) & 15ull);
            out[t] = (float)prev;        // path[t-1] = chain[t]
            tag = prev;
        }
    }
}

// ---------------- launch ----------------
extern "C" void kernel_launch(void* const* d_in, const int* in_sizes, int n_in,
                              void* d_out, int out_size)
{
    const int*   sent  = (const int*)d_in[0];
    const float* embt  = (const float*)d_in[1];
    const float* Wih_f = (const float*)d_in[2];
    const float* Whh_f = (const float*)d_in[3];
    const float* bih_f = (const float*)d_in[4];
    const float* bhh_f = (const float*)d_in[5];
    const float* Wih_b = (const float*)d_in[6];
    const float* Whh_b = (const float*)d_in[7];
    const float* bih_b = (const float*)d_in[8];
    const float* bhh_b = (const float*)d_in[9];
    const float* W_out = (const float*)d_in[10];
    const float* b_out = (const float*)d_in[11];
    const float* trans = (const float*)d_in[12];
    float* out = (float*)d_out;

    init_kernel<<<8, 1024>>>();
    dim3 g(T / 32, G4 / 256, 2);
    xg_kernel<<<g, 256>>>(sent, embt, Wih_f, bih_f, bhh_f, Wih_b, bih_b, bhh_b);
    lstm_kernel<<<2 * NB, 256>>>(Whh_f, Whh_b);
    feats_kernel<<<256, 128>>>(W_out, b_out);
    viterbi_kernel<<<1, 32>>>(trans, out);
}

// round 13
// speedup vs baseline: 1.8843x; 1.0107x over previous
#include <cuda_runtime.h>
#include <math.h>

#define T 4096
#define E 300
#define HID 512
#define G4 2048          // 4*HID
#define TAGS 12
#define NEGV -10000.0f
#define NB 32            // persistent blocks per direction in LSTM kernel

// ---------------- static device scratch (no allocations allowed) ----------------
__device__ float d_xg[2][T * G4];          // 2 x 32 MB: precomputed input projections
__device__ float d_Hs[2][T * HID];         // 2 x 8 MB : per-step hidden states
__device__ unsigned int d_cnt[2][T];       // per-(dir,step) arrival counters
__device__ float d_feats[T * TAGS];
__device__ unsigned long long d_bp[T];     // packed backpointers: 12 nibbles per step

// fma.rn.f32x2 (FFMA2): numerics cleared vs scalar FFMA (R3/R4 bit-identical)
#define FMA2(d, a, b, c) \
    asm("fma.rn.f32x2 %0, %1, %2, %3;" : "=l"(d) : "l"(a), "l"(b), "l"(c))

// MUFU.TANH path cleared in R10/R11 (passed, rel_err 5.7e-6)
__device__ __forceinline__ float tanh_fast(float x) {
    float r;
    asm("tanh.approx.f32 %0, %1;" : "=f"(r) : "f"(x));
    return r;
}
__device__ __forceinline__ float sigmoid_fast(float x) {
    return fmaf(tanh_fast(0.5f * x), 0.5f, 0.5f);
}

// ---------------- zero step counters (graph replays reuse state) ----------------
__global__ void init_kernel() {
    int i = blockIdx.x * 1024 + threadIdx.x;
    if (i < 2 * T) ((unsigned int*)d_cnt)[i] = 0u;
}

// ---------------- xg = emb[sentence] @ Wih^T + (bih + bhh), both dirs ----------------
// (UNCHANGED from R12)
__global__ void __launch_bounds__(256) xg_kernel(
    const int*   __restrict__ sent,
    const float* __restrict__ embt,
    const float* __restrict__ Wih_f,
    const float* __restrict__ bih_f,
    const float* __restrict__ bhh_f,
    const float* __restrict__ Wih_b,
    const float* __restrict__ bih_b,
    const float* __restrict__ bhh_b)
{
    const int dir = blockIdx.z;
    const float* Wih = dir ? Wih_b : Wih_f;
    const float* bih = dir ? bih_b : bih_f;
    const float* bhh = dir ? bhh_b : bhh_f;

    __shared__ __align__(16) float es[E * 32];   // es[k*32 + t]
    int t0 = blockIdx.x * 32;
    for (int i = threadIdx.x; i < 32 * E; i += 256) {
        int tt = i / E, k = i - tt * E;
        es[k * 32 + tt] = embt[(long long)sent[t0 + tt] * E + k];
    }
    __syncthreads();

    int r = blockIdx.y * 256 + threadIdx.x;
    const float4* w4 = (const float4*)(Wih + (long long)r * E);   // E=300 = 75 float4
    float bias = bih[r] + bhh[r];

    unsigned long long acc2[16];                  // 32 fp32 accumulators, packed
    {
        unsigned bb = __float_as_uint(bias);
        unsigned long long b2;
        asm("mov.b64 %0, {%1,%1};" : "=l"(b2) : "r"(bb));
#pragma unroll
        for (int i = 0; i < 16; i++) acc2[i] = b2;
    }

    for (int ko = 0; ko < 75; ko++) {
        float4 wq = __ldg(w4 + ko);
#pragma unroll
        for (int j = 0; j < 4; j++) {
            float wv = (j == 0) ? wq.x : (j == 1) ? wq.y : (j == 2) ? wq.z : wq.w;
            unsigned wb = __float_as_uint(wv);
            unsigned long long wvv;
            asm("mov.b64 %0, {%1,%1};" : "=l"(wvv) : "r"(wb));
            const ulonglong2* e2 = (const ulonglong2*)(es + (4 * ko + j) * 32);
#pragma unroll
            for (int q = 0; q < 8; q++) {
                ulonglong2 ev = e2[q];            // broadcast LDS.128
                FMA2(acc2[2 * q],     wvv, ev.x, acc2[2 * q]);
                FMA2(acc2[2 * q + 1], wvv, ev.y, acc2[2 * q + 1]);
            }
        }
    }

    float* xg = d_xg[dir];
#pragma unroll
    for (int i = 0; i < 16; i++) {
        float lo, hi;
        asm("mov.b64 {%0,%1}, %2;" : "=f"(lo), "=f"(hi) : "l"(acc2[i]));
        xg[(long long)(t0 + 2 * i)     * G4 + r] = lo;
        xg[(long long)(t0 + 2 * i + 1) * G4 + r] = hi;
    }
}

// ---------------- persistent BiLSTM recurrence (UNCHANGED from R11/R12 best) ----------------
__global__ void __launch_bounds__(256, 1) lstm_kernel(
    const float* __restrict__ Whh_f,
    const float* __restrict__ Whh_b)
{
    const int bx  = blockIdx.x;
    const int dir = bx >> 5;
    const int b   = bx & 31;
    const float* Whh = dir ? Whh_b : Whh_f;
    const float* xg  = d_xg[dir];
    float* Hst = d_Hs[dir];
    unsigned int* cnt = d_cnt[dir];

    const int tid = threadIdx.x;
    const int w = tid >> 5, l = tid & 31;
    const int cc = w >> 1;                  // 0..3 column chunk (128 cols)
    const int lr = (w & 1) * 32 + l;        // 0..63 local gate row
    const int grow = ((lr >> 4) << 9) + b * 16 + (lr & 15);  // global gate row

    unsigned long long wreg[64];
    {
        const ulonglong2* wp =
            (const ulonglong2*)(Whh + (long long)grow * HID + cc * 128);
#pragma unroll
        for (int i = 0; i < 32; i++) {
            ulonglong2 v = wp[i];
            wreg[2 * i]     = v.x;
            wreg[2 * i + 1] = v.y;
        }
    }

    __shared__ __align__(16) float h_sh[HID];
    __shared__ float part[4][64];

    float c = 0.f;                 // cell state (warp 0 lanes 0-15)
    float xgv[4] = {0.f, 0.f, 0.f, 0.f};

    h_sh[tid] = 0.f;
    h_sh[tid + 256] = 0.f;
    if (w == 0 && l < 16) {
        int t0 = dir ? (T - 1) : 0;
#pragma unroll
        for (int g = 0; g < 4; g++)
            xgv[g] = xg[(long long)t0 * G4 + (g << 9) + b * 16 + l];
    }
    __syncthreads();

    for (int s = 0; s < T; s++) {
        const int t = dir ? (T - 1 - s) : s;

        // ---- partial dot: lane gate-row x 128-col chunk (FFMA2) ----
        {
            unsigned long long a0 = 0ull, a1 = 0ull;
            const ulonglong2* h2 = (const ulonglong2*)(h_sh + (cc << 7));
#pragma unroll
            for (int i = 0; i < 32; i++) {
                ulonglong2 hv = h2[i];   // broadcast LDS.128 (uniform address)
                FMA2(a0, wreg[2 * i],     hv.x, a0);
                FMA2(a1, wreg[2 * i + 1], hv.y, a1);
            }
            float x0, x1, x2, x3;
            asm("mov.b64 {%0,%1}, %2;" : "=f"(x0), "=f"(x1) : "l"(a0));
            asm("mov.b64 {%0,%1}, %2;" : "=f"(x2), "=f"(x3) : "l"(a1));
            part[cc][lr] = (x0 + x1) + (x2 + x3);
        }
        __syncthreads();   // A: all partials in smem

        if (w == 0) {
            if (l < 16) {
                float g0 = part[0][l]      + part[1][l]      + part[2][l]      + part[3][l]      + xgv[0];
                float g1 = part[0][16 + l] + part[1][16 + l] + part[2][16 + l] + part[3][16 + l] + xgv[1];
                float g2 = part[0][32 + l] + part[1][32 + l] + part[2][32 + l] + part[3][32 + l] + xgv[2];
                float g3 = part[0][48 + l] + part[1][48 + l] + part[2][48 + l] + part[3][48 + l] + xgv[3];

                float ig = sigmoid_fast(g0);
                float fg = sigmoid_fast(g1);
                float og = sigmoid_fast(g3);
                float tg = tanh_fast(g2);
                c = fg * c + ig * tg;
                float hh = og * tanh_fast(c);

                asm volatile("st.global.cg.f32 [%0], %1;"
                             :: "l"(Hst + (long long)t * HID + b * 16 + l),
                                "f"(hh) : "memory");

                if (s + 1 < T) {
                    int tn = dir ? (t - 1) : (t + 1);
#pragma unroll
                    for (int g = 0; g < 4; g++)
                        xgv[g] = __ldcg(xg + (long long)tn * G4 + (g << 9) + b * 16 + l);
                }
            }
            __syncwarp();   // all lanes' h stores ordered before the release
            if (l == 0) {
                asm volatile("red.release.gpu.global.add.u32 [%0], %1;"
                             :: "l"(cnt + t), "r"(1u) : "memory");
            }
        } else if (w == 1 && s + 1 < T) {
            unsigned v;
            do {
                asm volatile("ld.acquire.gpu.global.u32 %0, [%1];"
                             : "=r"(v) : "l"(cnt + t) : "memory");
            } while (v < (unsigned)NB);

            const float4* hp4 = (const float4*)(Hst + (long long)t * HID);
            float4 r0 = __ldcg(hp4 + l);
            float4 r1 = __ldcg(hp4 + 32 + l);
            float4 r2 = __ldcg(hp4 + 64 + l);
            float4 r3 = __ldcg(hp4 + 96 + l);
            float4* hs4 = (float4*)h_sh;
            hs4[l]      = r0;
            hs4[32 + l] = r1;
            hs4[64 + l] = r2;
            hs4[96 + l] = r3;
        }
        __syncthreads();   // B: h(t) staged in smem for next step
    }
}

// ---------------- feats = [h_f, h_b] @ W_out^T + b_out ----------------
// grid 512, block 128, 8 timesteps per block.
__global__ void __launch_bounds__(128) feats_kernel(
    const float* __restrict__ W_out,
    const float* __restrict__ b_out)
{
    __shared__ __align__(16) float hb[2 * HID];
    int tid = threadIdx.x;
    int r = tid >> 3, cs = tid & 7;

    for (int tt = 0; tt < 8; tt++) {
        int t = blockIdx.x * 8 + tt;
        __syncthreads();
        ((float4*)hb)[tid]       = ((const float4*)(d_Hs[0] + (long long)t * HID))[tid];
        ((float4*)hb)[128 + tid] = ((const float4*)(d_Hs[1] + (long long)t * HID))[tid];
        __syncthreads();
        if (tid < 96) {
            const float4* wv = (const float4*)(W_out + r * 1024 + cs * 128);
            const float4* hv = (const float4*)(hb + cs * 128);
            float s0 = 0.f, s1 = 0.f, s2 = 0.f, s3 = 0.f;
#pragma unroll
            for (int i = 0; i < 32; i++) {
                float4 a = __ldg(wv + i);
                float4 bq = hv[i];
                s0 += a.x * bq.x; s1 += a.y * bq.y;
                s2 += a.z * bq.z; s3 += a.w * bq.w;
            }
            float sum = (s0 + s1) + (s2 + s3);
#pragma unroll
            for (int o = 4; o >= 1; o >>= 1)
                sum += __shfl_down_sync(0xffffffffu, sum, o);
            if (cs == 0)
                d_feats[t * TAGS + r] = sum + b_out[r];
        }
    }
}

// ---------------- Viterbi: forward scan + packed backtrace ----------------
// Depth-4 pairwise argmax tree, ordered lower-index-first with >= ties
// == jnp.argmax first-occurrence semantics. Comparisons exact; the v[p]
// computation (shfl(fv,p)+tr[p]) is unchanged -> bit-identical fv path.
#define AMAX2(mv, mi, xv, xi, yv, yi) \
    { bool _ge = (xv) >= (yv); mv = _ge ? (xv) : (yv); mi = _ge ? (xi) : (yi); }

__global__ void viterbi_kernel(const float* __restrict__ trans,
                               float* __restrict__ out)
{
    __shared__ unsigned long long bps[T];
    int l = threadIdx.x;

    float tr[TAGS];
    if (l < TAGS) {
#pragma unroll
        for (int p = 0; p < TAGS; p++) tr[p] = trans[l * TAGS + p];
    } else {
#pragma unroll
        for (int p = 0; p < TAGS; p++) tr[p] = 0.f;
    }

    float fv = (l == 10) ? 0.f : NEGV;   // START = 10
    float featnext = (l < TAGS) ? d_feats[l] : 0.f;

    for (int t = 0; t < T; t++) {
        float feat = featnext;
        if (t + 1 < T && l < TAGS) featnext = d_feats[(t + 1) * TAGS + l];

        float v[TAGS];
#pragma unroll
        for (int p = 0; p < TAGS; p++)
            v[p] = __shfl_sync(0xffffffffu, fv, p) + tr[p];

        // pairwise argmax tree (depth 4), first-index ties
        float a0v, a1v, a2v, a3v, a4v, a5v;  int a0i, a1i, a2i, a3i, a4i, a5i;
        AMAX2(a0v, a0i, v[0],  0,  v[1],  1);
        AMAX2(a1v, a1i, v[2],  2,  v[3],  3);
        AMAX2(a2v, a2i, v[4],  4,  v[5],  5);
        AMAX2(a3v, a3i, v[6],  6,  v[7],  7);
        AMAX2(a4v, a4i, v[8],  8,  v[9],  9);
        AMAX2(a5v, a5i, v[10], 10, v[11], 11);
        float b0v, b1v, b2v;  int b0i, b1i, b2i;
        AMAX2(b0v, b0i, a0v, a0i, a1v, a1i);
        AMAX2(b1v, b1i, a2v, a2i, a3v, a3i);
        AMAX2(b2v, b2i, a4v, a4i, a5v, a5i);
        float c0v;  int c0i;
        AMAX2(c0v, c0i, b0v, b0i, b1v, b1i);
        float m;  int am;
        AMAX2(m, am, c0v, c0i, b2v, b2i);

        unsigned lo = (l < 8)              ? ((unsigned)am << (4 * l))       : 0u;
        unsigned hi = (l >= 8 && l < TAGS) ? ((unsigned)am << (4 * (l - 8))) : 0u;
        lo = __reduce_add_sync(0xffffffffu, lo);
        hi = __reduce_add_sync(0xffffffffu, hi);
        if (l == 0) bps[t] = ((unsigned long long)hi << 32) | lo;

        fv = m + feat;
    }

    float term;
    if (l < TAGS) term = fv + trans[11 * TAGS + l];
    else          term = -3.4e38f;
    if (l == 11 || l == 10) term = NEGV;

    int best = 0; float sc = -3.4e38f;
#pragma unroll
    for (int p = 0; p < TAGS; p++) {
        float v = __shfl_sync(0xffffffffu, term, p);
        if (v > sc) { sc = v; best = p; }
    }

    __syncwarp();

    if (l == 0) {
        out[0] = sc;
        out[T] = (float)best;            // path[T-1]
        int tag = best;
        for (int t = T - 1; t >= 1; t--) {
            int prev = (int)((bps[t] >> (4 * tag)) & 15ull);
            out[t] = (float)prev;        // path[t-1] = chain[t]
            tag = prev;
        }
    }
}

// ---------------- launch ----------------
extern "C" void kernel_launch(void* const* d_in, const int* in_sizes, int n_in,
                              void* d_out, int out_size)
{
    const int*   sent  = (const int*)d_in[0];
    const float* embt  = (const float*)d_in[1];
    const float* Wih_f = (const float*)d_in[2];
    const float* Whh_f = (const float*)d_in[3];
    const float* bih_f = (const float*)d_in[4];
    const float* bhh_f = (const float*)d_in[5];
    const float* Wih_b = (const float*)d_in[6];
    const float* Whh_b = (const float*)d_in[7];
    const float* bih_b = (const float*)d_in[8];
    const float* bhh_b = (const float*)d_in[9];
    const float* W_out = (const float*)d_in[10];
    const float* b_out = (const float*)d_in[11];
    const float* trans = (const float*)d_in[12];
    float* out = (float*)d_out;

    init_kernel<<<8, 1024>>>();
    dim3 g(T / 32, G4 / 256, 2);
    xg_kernel<<<g, 256>>>(sent, embt, Wih_f, bih_f, bhh_f, Wih_b, bih_b, bhh_b);
    lstm_kernel<<<2 * NB, 256>>>(Whh_f, Whh_b);
    feats_kernel<<<512, 128>>>(W_out, b_out);
    viterbi_kernel<<<1, 32>>>(trans, out);
}

// round 14
// speedup vs baseline: 1.8898x; 1.0029x over previous
#include <cuda_runtime.h>
#include <math.h>

#define T 4096
#define E 300
#define HID 512
#define G4 2048          // 4*HID
#define TAGS 12
#define NEGV -10000.0f
#define NB 32            // persistent blocks per direction in LSTM kernel

// ---------------- static device scratch (no allocations allowed) ----------------
__device__ float d_xg[2][T * G4];          // 2 x 32 MB: precomputed input projections
__device__ float d_Hs[2][T * HID];         // 2 x 8 MB : per-step hidden states
__device__ unsigned int d_cnt[2][T];       // per-(dir,step) arrival counters
__device__ float d_feats[T * TAGS];

// fma.rn.f32x2 (FFMA2): numerics cleared vs scalar FFMA (R3/R4 bit-identical)
#define FMA2(d, a, b, c) \
    asm("fma.rn.f32x2 %0, %1, %2, %3;" : "=l"(d) : "l"(a), "l"(b), "l"(c))

// MUFU.TANH path cleared in R10/R11 (passed, rel_err 5.7e-6)
__device__ __forceinline__ float tanh_fast(float x) {
    float r;
    asm("tanh.approx.f32 %0, %1;" : "=f"(r) : "f"(x));
    return r;
}
__device__ __forceinline__ float sigmoid_fast(float x) {
    return fmaf(tanh_fast(0.5f * x), 0.5f, 0.5f);
}

// ---------------- zero step counters (graph replays reuse state) ----------------
__global__ void init_kernel() {
    int i = blockIdx.x * 1024 + threadIdx.x;
    if (i < 2 * T) ((unsigned int*)d_cnt)[i] = 0u;
}

// ---------------- xg = emb[sentence] @ Wih^T + (bih + bhh), both dirs ----------------
// (UNCHANGED from R12/R13)
__global__ void __launch_bounds__(256) xg_kernel(
    const int*   __restrict__ sent,
    const float* __restrict__ embt,
    const float* __restrict__ Wih_f,
    const float* __restrict__ bih_f,
    const float* __restrict__ bhh_f,
    const float* __restrict__ Wih_b,
    const float* __restrict__ bih_b,
    const float* __restrict__ bhh_b)
{
    const int dir = blockIdx.z;
    const float* Wih = dir ? Wih_b : Wih_f;
    const float* bih = dir ? bih_b : bih_f;
    const float* bhh = dir ? bhh_b : bhh_f;

    __shared__ __align__(16) float es[E * 32];   // es[k*32 + t]
    int t0 = blockIdx.x * 32;
    for (int i = threadIdx.x; i < 32 * E; i += 256) {
        int tt = i / E, k = i - tt * E;
        es[k * 32 + tt] = embt[(long long)sent[t0 + tt] * E + k];
    }
    __syncthreads();

    int r = blockIdx.y * 256 + threadIdx.x;
    const float4* w4 = (const float4*)(Wih + (long long)r * E);   // E=300 = 75 float4
    float bias = bih[r] + bhh[r];

    unsigned long long acc2[16];                  // 32 fp32 accumulators, packed
    {
        unsigned bb = __float_as_uint(bias);
        unsigned long long b2;
        asm("mov.b64 %0, {%1,%1};" : "=l"(b2) : "r"(bb));
#pragma unroll
        for (int i = 0; i < 16; i++) acc2[i] = b2;
    }

    for (int ko = 0; ko < 75; ko++) {
        float4 wq = __ldg(w4 + ko);
#pragma unroll
        for (int j = 0; j < 4; j++) {
            float wv = (j == 0) ? wq.x : (j == 1) ? wq.y : (j == 2) ? wq.z : wq.w;
            unsigned wb = __float_as_uint(wv);
            unsigned long long wvv;
            asm("mov.b64 %0, {%1,%1};" : "=l"(wvv) : "r"(wb));
            const ulonglong2* e2 = (const ulonglong2*)(es + (4 * ko + j) * 32);
#pragma unroll
            for (int q = 0; q < 8; q++) {
                ulonglong2 ev = e2[q];            // broadcast LDS.128
                FMA2(acc2[2 * q],     wvv, ev.x, acc2[2 * q]);
                FMA2(acc2[2 * q + 1], wvv, ev.y, acc2[2 * q + 1]);
            }
        }
    }

    float* xg = d_xg[dir];
#pragma unroll
    for (int i = 0; i < 16; i++) {
        float lo, hi;
        asm("mov.b64 {%0,%1}, %2;" : "=f"(lo), "=f"(hi) : "l"(acc2[i]));
        xg[(long long)(t0 + 2 * i)     * G4 + r] = lo;
        xg[(long long)(t0 + 2 * i + 1) * G4 + r] = hi;
    }
}

// ---------------- persistent BiLSTM recurrence ----------------
// 64 blocks (32 fwd, 32 bwd), 256 threads; all co-resident.
// Block b owns 16 hidden units -> 64 Whh gate rows (local row lr: gate=lr>>4,
// unit=lr&15). NEW dot layout (R=2 blocking): warp w owns local rows
// [8w, 8w+8); lane l: row pair p=l>>3 (rows 8w+2p, 8w+2p+1), col chunk
// cI=l&7 (64 cols). Each h 16B chunk feeds BOTH rows -> 16 LDS.128/thread
// (halved). Rotated iteration k=(i+cI)&15 makes the 8 chunk-groups hit
// disjoint bank quads -> 1 phase per LDS.128. Width-8 shfl reduce yields
// COMPLETE row sums -> part_full[64]; warp0's reduce is 4 LDS.
// Exchange protocol UNCHANGED from R11/R13 (counter + acquire poll + reload).
__global__ void __launch_bounds__(256, 1) lstm_kernel(
    const float* __restrict__ Whh_f,
    const float* __restrict__ Whh_b)
{
    const int bx  = blockIdx.x;
    const int dir = bx >> 5;
    const int b   = bx & 31;
    const float* Whh = dir ? Whh_b : Whh_f;
    const float* xg  = d_xg[dir];
    float* Hst = d_Hs[dir];
    unsigned int* cnt = d_cnt[dir];

    const int tid = threadIdx.x;
    const int w = tid >> 5, l = tid & 31;
    const int p  = l >> 3;                  // 0..3 row pair within warp
    const int cI = l & 7;                   // 0..7 col chunk (64 cols)
    const int lr0 = 8 * w + 2 * p;          // local gate rows
    const int lr1 = lr0 + 1;
    const int grow0 = ((lr0 >> 4) << 9) + b * 16 + (lr0 & 15);
    const int grow1 = ((lr1 >> 4) << 9) + b * 16 + (lr1 & 15);

    // weights: 2 rows x 64 cols = 128 fp32 as 64 u64 pairs, in rotated order
    unsigned long long w0reg[32], w1reg[32];
#pragma unroll
    for (int i = 0; i < 16; i++) {
        int k = (i + cI) & 15;
        ulonglong2 v0 = *(const ulonglong2*)(Whh + (long long)grow0 * HID + cI * 64 + 4 * k);
        ulonglong2 v1 = *(const ulonglong2*)(Whh + (long long)grow1 * HID + cI * 64 + 4 * k);
        w0reg[2 * i] = v0.x; w0reg[2 * i + 1] = v0.y;
        w1reg[2 * i] = v1.x; w1reg[2 * i + 1] = v1.y;
    }

    __shared__ __align__(16) float h_sh[HID];
    __shared__ __align__(8) float part_full[64];   // complete gate-row sums

    float c = 0.f;                 // cell state (warp 0 lanes 0-15)
    float xgv[4] = {0.f, 0.f, 0.f, 0.f};

    h_sh[tid] = 0.f;
    h_sh[tid + 256] = 0.f;
    if (w == 0 && l < 16) {
        int t0 = dir ? (T - 1) : 0;
#pragma unroll
        for (int g = 0; g < 4; g++)
            xgv[g] = xg[(long long)t0 * G4 + (g << 9) + b * 16 + l];
    }
    __syncthreads();

    for (int s = 0; s < T; s++) {
        const int t = dir ? (T - 1 - s) : s;

        // ---- dot: 2 rows x 64-col chunk, rotated conflict-free LDS ----
        {
            unsigned long long a00 = 0ull, a01 = 0ull, a10 = 0ull, a11 = 0ull;
            const ulonglong2* h2 = (const ulonglong2*)h_sh;
#pragma unroll
            for (int i = 0; i < 16; i++) {
                int k = (i + cI) & 15;
                ulonglong2 hv = h2[(cI << 4) + k];   // 1-phase LDS.128
                FMA2(a00, w0reg[2 * i],     hv.x, a00);
                FMA2(a01, w0reg[2 * i + 1], hv.y, a01);
                FMA2(a10, w1reg[2 * i],     hv.x, a10);
                FMA2(a11, w1reg[2 * i + 1], hv.y, a11);
            }
            float x0, x1, x2, x3, y0, y1, y2, y3;
            asm("mov.b64 {%0,%1}, %2;" : "=f"(x0), "=f"(x1) : "l"(a00));
            asm("mov.b64 {%0,%1}, %2;" : "=f"(x2), "=f"(x3) : "l"(a01));
            asm("mov.b64 {%0,%1}, %2;" : "=f"(y0), "=f"(y1) : "l"(a10));
            asm("mov.b64 {%0,%1}, %2;" : "=f"(y2), "=f"(y3) : "l"(a11));
            float s0 = (x0 + x1) + (x2 + x3);
            float s1 = (y0 + y1) + (y2 + y3);
            // width-8 pairwise reduce over the 8 col chunks
            s0 += __shfl_down_sync(0xffffffffu, s0, 4, 8);
            s1 += __shfl_down_sync(0xffffffffu, s1, 4, 8);
            s0 += __shfl_down_sync(0xffffffffu, s0, 2, 8);
            s1 += __shfl_down_sync(0xffffffffu, s1, 2, 8);
            s0 += __shfl_down_sync(0xffffffffu, s0, 1, 8);
            s1 += __shfl_down_sync(0xffffffffu, s1, 1, 8);
            if (cI == 0)
                ((float2*)part_full)[(w << 2) + p] = make_float2(s0, s1);
        }
        __syncthreads();   // A: complete row sums in smem

        if (w == 0) {
            if (l < 16) {
                float g0 = part_full[l]      + xgv[0];
                float g1 = part_full[16 + l] + xgv[1];
                float g2 = part_full[32 + l] + xgv[2];
                float g3 = part_full[48 + l] + xgv[3];

                float ig = sigmoid_fast(g0);
                float fg = sigmoid_fast(g1);
                float og = sigmoid_fast(g3);
                float tg = tanh_fast(g2);
                c = fg * c + ig * tg;
                float hh = og * tanh_fast(c);

                asm volatile("st.global.cg.f32 [%0], %1;"
                             :: "l"(Hst + (long long)t * HID + b * 16 + l),
                                "f"(hh) : "memory");

                if (s + 1 < T) {
                    int tn = dir ? (t - 1) : (t + 1);
#pragma unroll
                    for (int g = 0; g < 4; g++)
                        xgv[g] = __ldcg(xg + (long long)tn * G4 + (g << 9) + b * 16 + l);
                }
            }
            __syncwarp();   // all lanes' h stores ordered before the release
            if (l == 0) {
                asm volatile("red.release.gpu.global.add.u32 [%0], %1;"
                             :: "l"(cnt + t), "r"(1u) : "memory");
            }
        } else if (w == 1 && s + 1 < T) {
            // ---- poll ONE counter word; 2 outstanding loads per sweep ----
            unsigned v0, v1;
            do {
                asm volatile("ld.acquire.gpu.global.u32 %0, [%1];"
                             : "=r"(v0) : "l"(cnt + t) : "memory");
                asm volatile("ld.acquire.gpu.global.u32 %0, [%1];"
                             : "=r"(v1) : "l"(cnt + t) : "memory");
            } while (v0 < (unsigned)NB && v1 < (unsigned)NB);

            // ---- bulk reload h(t): 4 coalesced float4 loads per lane ----
            const float4* hp4 = (const float4*)(Hst + (long long)t * HID);
            float4 r0 = __ldcg(hp4 + l);
            float4 r1 = __ldcg(hp4 + 32 + l);
            float4 r2 = __ldcg(hp4 + 64 + l);
            float4 r3 = __ldcg(hp4 + 96 + l);
            float4* hs4 = (float4*)h_sh;
            hs4[l]      = r0;
            hs4[32 + l] = r1;
            hs4[64 + l] = r2;
            hs4[96 + l] = r3;
        }
        __syncthreads();   // B: h(t) staged in smem for next step
    }
}

// ---------------- feats = [h_f, h_b] @ W_out^T + b_out ----------------
// grid 512, block 128, 8 timesteps per block. (UNCHANGED from R13)
__global__ void __launch_bounds__(128) feats_kernel(
    const float* __restrict__ W_out,
    const float* __restrict__ b_out)
{
    __shared__ __align__(16) float hb[2 * HID];
    int tid = threadIdx.x;
    int r = tid >> 3, cs = tid & 7;

    for (int tt = 0; tt < 8; tt++) {
        int t = blockIdx.x * 8 + tt;
        __syncthreads();
        ((float4*)hb)[tid]       = ((const float4*)(d_Hs[0] + (long long)t * HID))[tid];
        ((float4*)hb)[128 + tid] = ((const float4*)(d_Hs[1] + (long long)t * HID))[tid];
        __syncthreads();
        if (tid < 96) {
            const float4* wv = (const float4*)(W_out + r * 1024 + cs * 128);
            const float4* hv = (const float4*)(hb + cs * 128);
            float s0 = 0.f, s1 = 0.f, s2 = 0.f, s3 = 0.f;
#pragma unroll
            for (int i = 0; i < 32; i++) {
                float4 a = __ldg(wv + i);
                float4 bq = hv[i];
                s0 += a.x * bq.x; s1 += a.y * bq.y;
                s2 += a.z * bq.z; s3 += a.w * bq.w;
            }
            float sum = (s0 + s1) + (s2 + s3);
#pragma unroll
            for (int o = 4; o >= 1; o >>= 1)
                sum += __shfl_down_sync(0xffffffffu, sum, o);
            if (cs == 0)
                d_feats[t * TAGS + r] = sum + b_out[r];
        }
    }
}

// ---------------- Viterbi (UNCHANGED from R13: pairwise argmax tree) ----------------
#define AMAX2(mv, mi, xv, xi, yv, yi) \
    { bool _ge = (xv) >= (yv); mv = _ge ? (xv) : (yv); mi = _ge ? (xi) : (yi); }

__global__ void viterbi_kernel(const float* __restrict__ trans,
                               float* __restrict__ out)
{
    __shared__ unsigned long long bps[T];
    int l = threadIdx.x;

    float tr[TAGS];
    if (l < TAGS) {
#pragma unroll
        for (int pq = 0; pq < TAGS; pq++) tr[pq] = trans[l * TAGS + pq];
    } else {
#pragma unroll
        for (int pq = 0; pq < TAGS; pq++) tr[pq] = 0.f;
    }

    float fv = (l == 10) ? 0.f : NEGV;   // START = 10
    float featnext = (l < TAGS) ? d_feats[l] : 0.f;

    for (int t = 0; t < T; t++) {
        float feat = featnext;
        if (t + 1 < T && l < TAGS) featnext = d_feats[(t + 1) * TAGS + l];

        float v[TAGS];
#pragma unroll
        for (int pq = 0; pq < TAGS; pq++)
            v[pq] = __shfl_sync(0xffffffffu, fv, pq) + tr[pq];

        float a0v, a1v, a2v, a3v, a4v, a5v;  int a0i, a1i, a2i, a3i, a4i, a5i;
        AMAX2(a0v, a0i, v[0],  0,  v[1],  1);
        AMAX2(a1v, a1i, v[2],  2,  v[3],  3);
        AMAX2(a2v, a2i, v[4],  4,  v[5],  5);
        AMAX2(a3v, a3i, v[6],  6,  v[7],  7);
        AMAX2(a4v, a4i, v[8],  8,  v[9],  9);
        AMAX2(a5v, a5i, v[10], 10, v[11], 11);
        float b0v, b1v, b2v;  int b0i, b1i, b2i;
        AMAX2(b0v, b0i, a0v, a0i, a1v, a1i);
        AMAX2(b1v, b1i, a2v, a2i, a3v, a3i);
        AMAX2(b2v, b2i, a4v, a4i, a5v, a5i);
        float c0v;  int c0i;
        AMAX2(c0v, c0i, b0v, b0i, b1v, b1i);
        float m;  int am;
        AMAX2(m, am, c0v, c0i, b2v, b2i);

        unsigned lo = (l < 8)              ? ((unsigned)am << (4 * l))       : 0u;
        unsigned hi = (l >= 8 && l < TAGS) ? ((unsigned)am << (4 * (l - 8))) : 0u;
        lo = __reduce_add_sync(0xffffffffu, lo);
        hi = __reduce_add_sync(0xffffffffu, hi);
        if (l == 0) bps[t] = ((unsigned long long)hi << 32) | lo;

        fv = m + feat;
    }

    float term;
    if (l < TAGS) term = fv + trans[11 * TAGS + l];
    else          term = -3.4e38f;
    if (l == 11 || l == 10) term = NEGV;

    int best = 0; float sc = -3.4e38f;
#pragma unroll
    for (int pq = 0; pq < TAGS; pq++) {
        float v2 = __shfl_sync(0xffffffffu, term, pq);
        if (v2 > sc) { sc = v2; best = pq; }
    }

    __syncwarp();

    if (l == 0) {
        out[0] = sc;
        out[T] = (float)best;            // path[T-1]
        int tag = best;
        for (int t = T - 1; t >= 1; t--) {
            int prev = (int)((bps[t] >> (4 * tag)) & 15ull);
            out[t] = (float)prev;        // path[t-1] = chain[t]
            tag = prev;
        }
    }
}

// ---------------- launch ----------------
extern "C" void kernel_launch(void* const* d_in, const int* in_sizes, int n_in,
                              void* d_out, int out_size)
{
    const int*   sent  = (const int*)d_in[0];
    const float* embt  = (const float*)d_in[1];
    const float* Wih_f = (const float*)d_in[2];
    const float* Whh_f = (const float*)d_in[3];
    const float* bih_f = (const float*)d_in[4];
    const float* bhh_f = (const float*)d_in[5];
    const float* Wih_b = (const float*)d_in[6];
    const float* Whh_b = (const float*)d_in[7];
    const float* bih_b = (const float*)d_in[8];
    const float* bhh_b = (const float*)d_in[9];
    const float* W_out = (const float*)d_in[10];
    const float* b_out = (const float*)d_in[11];
    const float* trans = (const float*)d_in[12];
    float* out = (float*)d_out;

    init_kernel<<<8, 1024>>>();
    dim3 g(T / 32, G4 / 256, 2);
    xg_kernel<<<g, 256>>>(sent, embt, Wih_f, bih_f, bhh_f, Wih_b, bih_b, bhh_b);
    lstm_kernel<<<2 * NB, 256>>>(Whh_f, Whh_b);
    feats_kernel<<<512, 128>>>(W_out, b_out);
    viterbi_kernel<<<1, 32>>>(trans, out);
}